// round 9
// baseline (speedup 1.0000x reference)
#include <cuda_runtime.h>
#include <math.h>

// Problem constants
#define NB   32
#define HG   24
#define WG   24
#define DIN  768
#define HID  384
#define G4   1536              // 4*HID
#define TT   24                // sequence length (both axes)
#define NSEQ 768               // sequences per direction (32*24)
#define MTOT 18432             // NB*HG*WG pixels

// Scratch (device globals -> no runtime allocation)
// z layout: [dir][t][seq][1536]; backward dirs stored time-reversed so the
// step kernel always consumes slot t.
__device__ float g_z[4u * TT * NSEQ * G4];          // 453 MB
__device__ float g_h[4][2][NSEQ * HID];             // ping-pong hidden state
__device__ float g_c[4][NSEQ * HID];                // cell state (in-place)

// ---------------------------------------------------------------------------
// Zero initial hidden/cell state (read buffer 0 + c). Must run every launch.
// ---------------------------------------------------------------------------
__global__ void zero_state_kernel() {
    int i = blockIdx.x * blockDim.x + threadIdx.x;
    const int n = 4 * NSEQ * HID;
    if (i < n) {
        int d = i / (NSEQ * HID);
        int r = i - d * (NSEQ * HID);
        g_h[d][0][r] = 0.0f;
        g_c[d][r]    = 0.0f;
    }
}

// ---------------------------------------------------------------------------
// Input projection: Z[d][t][seq][:] = X @ Wx_d + b_d   (M=18432, K=768, N=6144)
// BM=128, BN=128, BK=8, 256 threads, 8x8 per thread.
// Each block's 128-col tile lies within a single direction (1536 % 128 == 0).
// ---------------------------------------------------------------------------
__global__ __launch_bounds__(256, 2) void input_gemm_kernel(
    const float* __restrict__ X,
    const float* __restrict__ Wx0, const float* __restrict__ Wx1,
    const float* __restrict__ Wx2, const float* __restrict__ Wx3,
    const float* __restrict__ b0,  const float* __restrict__ b1,
    const float* __restrict__ b2,  const float* __restrict__ b3)
{
    const int tid = threadIdx.x;
    const int bn  = blockIdx.x;              // 0..47  (6144/128)
    const int bm  = blockIdx.y;              // 0..143 (18432/128)
    const int d   = (bn * 128) / G4;         // direction 0..3
    const int n0  = (bn * 128) % G4;
    const int m0  = bm * 128;

    const float* Wd = (d == 0) ? Wx0 : (d == 1) ? Wx1 : (d == 2) ? Wx2 : Wx3;
    const float* bd = (d == 0) ? b0  : (d == 1) ? b1  : (d == 2) ? b2  : b3;

    __shared__ float As[8][128];   // [k][m]
    __shared__ float Bs[8][128];   // [k][n]

    const int ty = tid / 16;       // 0..15 -> row group
    const int tx = tid % 16;       // 0..15 -> col group

    // global load indices
    const int arow = tid / 2;          // 0..127
    const int ak   = (tid & 1) * 4;    // 0 or 4
    const int brow = tid / 32;         // 0..7
    const int bcol = (tid % 32) * 4;   // 0..124

    float acc[8][8];
#pragma unroll
    for (int r = 0; r < 8; r++)
#pragma unroll
        for (int c = 0; c < 8; c++) acc[r][c] = 0.0f;

    for (int k = 0; k < DIN; k += 8) {
        float4 av = *(const float4*)(X + (long)(m0 + arow) * DIN + k + ak);
        float4 bv = *(const float4*)(Wd + (long)(k + brow) * G4 + n0 + bcol);
        __syncthreads();
        As[ak + 0][arow] = av.x;
        As[ak + 1][arow] = av.y;
        As[ak + 2][arow] = av.z;
        As[ak + 3][arow] = av.w;
        *(float4*)&Bs[brow][bcol] = bv;
        __syncthreads();
#pragma unroll
        for (int kk = 0; kk < 8; kk++) {
            float a[8], b[8];
            *(float4*)&a[0] = *(const float4*)&As[kk][ty * 8];
            *(float4*)&a[4] = *(const float4*)&As[kk][ty * 8 + 4];
            *(float4*)&b[0] = *(const float4*)&Bs[kk][tx * 8];
            *(float4*)&b[4] = *(const float4*)&Bs[kk][tx * 8 + 4];
#pragma unroll
            for (int r = 0; r < 8; r++)
#pragma unroll
                for (int c = 0; c < 8; c++) acc[r][c] += a[r] * b[c];
        }
    }

    // bias (same 8 columns for every row this thread owns)
    float bias[8];
    *(float4*)&bias[0] = *(const float4*)(bd + n0 + tx * 8);
    *(float4*)&bias[4] = *(const float4*)(bd + n0 + tx * 8 + 4);

#pragma unroll
    for (int r = 0; r < 8; r++) {
        const int p   = m0 + ty * 8 + r;         // pixel index (b,hg,wg)
        const int bb  = p / (HG * WG);
        const int rem = p - bb * (HG * WG);
        const int hg  = rem / WG;
        const int wg  = rem - hg * WG;
        int seq, t;
        if (d == 0)      { seq = bb * HG + hg; t = wg;          }
        else if (d == 1) { seq = bb * HG + hg; t = (TT - 1) - wg; }
        else if (d == 2) { seq = bb * WG + wg; t = hg;          }
        else             { seq = bb * WG + wg; t = (TT - 1) - hg; }

        float* zp = g_z + ((long)(d * TT + t) * NSEQ + seq) * G4 + n0 + tx * 8;
        float4 v0 = make_float4(acc[r][0] + bias[0], acc[r][1] + bias[1],
                                acc[r][2] + bias[2], acc[r][3] + bias[3]);
        float4 v1 = make_float4(acc[r][4] + bias[4], acc[r][5] + bias[5],
                                acc[r][6] + bias[6], acc[r][7] + bias[7]);
        *(float4*)(zp)     = v0;
        *(float4*)(zp + 4) = v1;
    }
}

// ---------------------------------------------------------------------------
// One LSTM time step, all 4 directions (blockIdx.z = dir).
// Block: 64 seqs x 32 hidden units (x 4 gates). K = 384.
// Thread (ty 0..7, tx 0..31): 8 seq rows, 1 hidden unit j, 4 gate accumulators.
// Reads h from ping buffer, writes h to pong buffer + d_out; c in place.
// ---------------------------------------------------------------------------
__global__ __launch_bounds__(256) void lstm_step_kernel(
    const float* __restrict__ Wh0, const float* __restrict__ Wh1,
    const float* __restrict__ Wh2, const float* __restrict__ Wh3,
    float* __restrict__ out, int t)
{
    const int tid = threadIdx.x;
    const int j0  = blockIdx.x * 32;   // hidden-unit tile (12 tiles)
    const int s0  = blockIdx.y * 64;   // sequence tile   (12 tiles)
    const int d   = blockIdx.z;        // direction

    const float* Wh   = (d == 0) ? Wh0 : (d == 1) ? Wh1 : (d == 2) ? Wh2 : Wh3;
    const float* hin  = g_h[d][t & 1];
    float*       hout = g_h[d][(t + 1) & 1];
    float*       cbuf = g_c[d];
    const float* zslab = g_z + (long)(d * TT + t) * NSEQ * G4;

    __shared__ float As[8][64];    // [k][seq]
    __shared__ float Bs[8][128];   // [k][gate*32 + lane]

    const int ty = tid / 32;       // 0..7
    const int tx = tid % 32;       // 0..31

    float acc[8][4];
#pragma unroll
    for (int r = 0; r < 8; r++)
#pragma unroll
        for (int g = 0; g < 4; g++) acc[r][g] = 0.0f;

    const int arow = tid / 2;          // 0..63 (only tid<128 load A)
    const int ak   = (tid & 1) * 4;

    for (int k = 0; k < HID; k += 8) {
        float4 av = make_float4(0.f, 0.f, 0.f, 0.f);
        if (tid < 128)
            av = *(const float4*)(hin + (s0 + arow) * HID + k + ak);
        const float* wrow = Wh + (long)(k + ty) * G4 + j0 + tx;
        float bv0 = wrow[0 * HID];
        float bv1 = wrow[1 * HID];
        float bv2 = wrow[2 * HID];
        float bv3 = wrow[3 * HID];
        __syncthreads();
        if (tid < 128) {
            As[ak + 0][arow] = av.x;
            As[ak + 1][arow] = av.y;
            As[ak + 2][arow] = av.z;
            As[ak + 3][arow] = av.w;
        }
        Bs[ty][0 * 32 + tx] = bv0;
        Bs[ty][1 * 32 + tx] = bv1;
        Bs[ty][2 * 32 + tx] = bv2;
        Bs[ty][3 * 32 + tx] = bv3;
        __syncthreads();
#pragma unroll
        for (int kk = 0; kk < 8; kk++) {
            float b0 = Bs[kk][tx];
            float b1 = Bs[kk][32 + tx];
            float b2 = Bs[kk][64 + tx];
            float b3 = Bs[kk][96 + tx];
            float a[8];
            *(float4*)&a[0] = *(const float4*)&As[kk][ty * 8];
            *(float4*)&a[4] = *(const float4*)&As[kk][ty * 8 + 4];
#pragma unroll
            for (int r = 0; r < 8; r++) {
                acc[r][0] += a[r] * b0;
                acc[r][1] += a[r] * b1;
                acc[r][2] += a[r] * b2;
                acc[r][3] += a[r] * b3;
            }
        }
    }

    const int j = j0 + tx;
#pragma unroll
    for (int r = 0; r < 8; r++) {
        const int s = s0 + ty * 8 + r;
        const float* zr = zslab + (long)s * G4;
        float gi = acc[r][0] + zr[0 * HID + j];
        float gf = acc[r][1] + zr[1 * HID + j];
        float gc = acc[r][2] + zr[2 * HID + j];
        float go = acc[r][3] + zr[3 * HID + j];

        float i_ = 1.0f / (1.0f + __expf(-gi));
        float f_ = 1.0f / (1.0f + __expf(-gf));
        float cd = tanhf(gc);
        float o_ = 1.0f / (1.0f + __expf(-go));

        float cn = f_ * cbuf[s * HID + j] + i_ * cd;
        cbuf[s * HID + j] = cn;
        float h = o_ * tanhf(cn);
        hout[s * HID + j] = h;

        // scatter to output: channel block = d*HID
        const int bb = s / 24;
        const int q  = s - bb * 24;
        int hg, wg;
        if (d == 0)      { hg = q; wg = t;            }
        else if (d == 1) { hg = q; wg = (TT - 1) - t; }
        else if (d == 2) { wg = q; hg = t;            }
        else             { wg = q; hg = (TT - 1) - t; }
        out[(long)((bb * HG + hg) * WG + wg) * G4 + d * HID + j] = h;
    }
}

// ---------------------------------------------------------------------------
// Launch
// ---------------------------------------------------------------------------
extern "C" void kernel_launch(void* const* d_in, const int* in_sizes, int n_in,
                              void* d_out, int out_size) {
    (void)in_sizes; (void)n_in; (void)out_size;
    const float* X     = (const float*)d_in[0];
    const float* hf_Wx = (const float*)d_in[1];
    const float* hf_Wh = (const float*)d_in[2];
    const float* hf_b  = (const float*)d_in[3];
    const float* hb_Wx = (const float*)d_in[4];
    const float* hb_Wh = (const float*)d_in[5];
    const float* hb_b  = (const float*)d_in[6];
    const float* vf_Wx = (const float*)d_in[7];
    const float* vf_Wh = (const float*)d_in[8];
    const float* vf_b  = (const float*)d_in[9];
    const float* vb_Wx = (const float*)d_in[10];
    const float* vb_Wh = (const float*)d_in[11];
    const float* vb_b  = (const float*)d_in[12];
    float* out = (float*)d_out;

    // 1. zero h0/c0
    {
        int n = 4 * NSEQ * HID;
        zero_state_kernel<<<(n + 255) / 256, 256>>>();
    }

    // 2. input projection for all 4 directions
    input_gemm_kernel<<<dim3(48, 144), 256>>>(
        X, hf_Wx, hb_Wx, vf_Wx, vb_Wx, hf_b, hb_b, vf_b, vb_b);

    // 3. 24 recurrent steps, all 4 directions per launch
    for (int t = 0; t < TT; t++) {
        lstm_step_kernel<<<dim3(HID / 32, NSEQ / 64, 4), 256>>>(
            hf_Wh, hb_Wh, vf_Wh, vb_Wh, out, t);
    }
}

// round 12
// speedup vs baseline: 1.0820x; 1.0820x over previous
#include <cuda_runtime.h>
#include <math.h>

// Problem constants
#define NB   32
#define HG   24
#define WG   24
#define DIN  768
#define HID  384
#define G4   1536              // 4*HID
#define TT   24                // sequence length (both axes)
#define NSEQ 768               // sequences per direction (32*24)
#define MTOT 18432             // NB*HG*WG pixels

typedef unsigned long long ull;

// Scratch (device globals -> no runtime allocation)
// z layout: [dir][t][seq][1536]; backward dirs stored time-reversed so the
// step kernel always consumes slot t.
__device__ float g_z[4u * TT * NSEQ * G4];          // 453 MB
__device__ float g_h[4][2][NSEQ * HID];             // ping-pong hidden state
__device__ float g_c[4][NSEQ * HID];                // cell state (in-place)

// packed f32x2 helpers (FFMA2 path — only reachable via PTX fma.rn.f32x2)
__device__ __forceinline__ ull pack_dup(float a) {
    ull d;
    asm("mov.b64 %0, {%1, %1};" : "=l"(d) : "f"(a));
    return d;
}
__device__ __forceinline__ void ffma2(ull& acc, ull a, ull b) {
    asm("fma.rn.f32x2 %0, %1, %2, %0;" : "+l"(acc) : "l"(a), "l"(b));
}
__device__ __forceinline__ float tanh_fast(float x) {
    float r;
    asm("tanh.approx.f32 %0, %1;" : "=f"(r) : "f"(x));
    return r;
}

// ---------------------------------------------------------------------------
// Input projection: Z[d][t][seq][:] = X @ Wx_d + b_d   (M=18432, K=768, N=6144)
// BM=128, BN=128, BK=8, 256 threads, 8x8 per thread, packed f32x2 FMA.
// ---------------------------------------------------------------------------
__global__ __launch_bounds__(256, 2) void input_gemm_kernel(
    const float* __restrict__ X,
    const float* __restrict__ Wx0, const float* __restrict__ Wx1,
    const float* __restrict__ Wx2, const float* __restrict__ Wx3,
    const float* __restrict__ b0,  const float* __restrict__ b1,
    const float* __restrict__ b2,  const float* __restrict__ b3)
{
    const int tid = threadIdx.x;
    const int bn  = blockIdx.x;              // 0..47  (6144/128)
    const int bm  = blockIdx.y;              // 0..143 (18432/128)
    const int d   = (bn * 128) / G4;         // direction 0..3
    const int n0  = (bn * 128) % G4;
    const int m0  = bm * 128;

    const float* Wd = (d == 0) ? Wx0 : (d == 1) ? Wx1 : (d == 2) ? Wx2 : Wx3;
    const float* bd = (d == 0) ? b0  : (d == 1) ? b1  : (d == 2) ? b2  : b3;

    __shared__ float As[8][128];   // [k][m]
    __shared__ float Bs[8][128];   // [k][n]

    const int ty = tid / 16;       // 0..15 -> row group
    const int tx = tid % 16;       // 0..15 -> col group

    const int arow = tid / 2;          // 0..127
    const int ak   = (tid & 1) * 4;    // 0 or 4
    const int brow = tid / 32;         // 0..7
    const int bcol = (tid % 32) * 4;   // 0..124

    ull acc2[8][4];                // [row][col-pair] packed f32x2
#pragma unroll
    for (int r = 0; r < 8; r++)
#pragma unroll
        for (int c = 0; c < 4; c++) acc2[r][c] = 0ULL;

    for (int k = 0; k < DIN; k += 8) {
        float4 av = *(const float4*)(X + (long)(m0 + arow) * DIN + k + ak);
        float4 bv = *(const float4*)(Wd + (long)(k + brow) * G4 + n0 + bcol);
        __syncthreads();
        As[ak + 0][arow] = av.x;
        As[ak + 1][arow] = av.y;
        As[ak + 2][arow] = av.z;
        As[ak + 3][arow] = av.w;
        *(float4*)&Bs[brow][bcol] = bv;
        __syncthreads();
#pragma unroll
        for (int kk = 0; kk < 8; kk++) {
            union { float4 f4; ull u2[2]; } bu0, bu1;
            bu0.f4 = *(const float4*)&Bs[kk][tx * 8];
            bu1.f4 = *(const float4*)&Bs[kk][tx * 8 + 4];
            float a[8];
            *(float4*)&a[0] = *(const float4*)&As[kk][ty * 8];
            *(float4*)&a[4] = *(const float4*)&As[kk][ty * 8 + 4];
#pragma unroll
            for (int r = 0; r < 8; r++) {
                ull ad = pack_dup(a[r]);
                ffma2(acc2[r][0], ad, bu0.u2[0]);
                ffma2(acc2[r][1], ad, bu0.u2[1]);
                ffma2(acc2[r][2], ad, bu1.u2[0]);
                ffma2(acc2[r][3], ad, bu1.u2[1]);
            }
        }
    }

    // bias (same 8 columns for every row this thread owns)
    float bias[8];
    *(float4*)&bias[0] = *(const float4*)(bd + n0 + tx * 8);
    *(float4*)&bias[4] = *(const float4*)(bd + n0 + tx * 8 + 4);

#pragma unroll
    for (int r = 0; r < 8; r++) {
        float accf[8];
#pragma unroll
        for (int c = 0; c < 4; c++) {
            union { ull u; float2 f; } v;
            v.u = acc2[r][c];
            accf[2 * c]     = v.f.x;
            accf[2 * c + 1] = v.f.y;
        }
        const int p   = m0 + ty * 8 + r;         // pixel index (b,hg,wg)
        const int bb  = p / (HG * WG);
        const int rem = p - bb * (HG * WG);
        const int hg  = rem / WG;
        const int wg  = rem - hg * WG;
        int seq, t;
        if (d == 0)      { seq = bb * HG + hg; t = wg;            }
        else if (d == 1) { seq = bb * HG + hg; t = (TT - 1) - wg; }
        else if (d == 2) { seq = bb * WG + wg; t = hg;            }
        else             { seq = bb * WG + wg; t = (TT - 1) - hg; }

        float* zp = g_z + ((long)(d * TT + t) * NSEQ + seq) * G4 + n0 + tx * 8;
        float4 v0 = make_float4(accf[0] + bias[0], accf[1] + bias[1],
                                accf[2] + bias[2], accf[3] + bias[3]);
        float4 v1 = make_float4(accf[4] + bias[4], accf[5] + bias[5],
                                accf[6] + bias[6], accf[7] + bias[7]);
        *(float4*)(zp)     = v0;
        *(float4*)(zp + 4) = v1;
    }
}

// ---------------------------------------------------------------------------
// One LSTM time step, all 4 directions (blockIdx.z = dir).
// Block: 64 seqs x 32 hidden units (x 4 gates). K = 384.
// Thread (ty 0..7, tx 0..31): 8 seq rows, 1 hidden unit j, 4 gate accumulators
// kept as two packed f32x2 pairs (i,f) and (c,o).
// t == 0 skips the recurrent GEMM entirely (h0 = 0, c0 = 0).
// ---------------------------------------------------------------------------
__global__ __launch_bounds__(256) void lstm_step_kernel(
    const float* __restrict__ Wh0, const float* __restrict__ Wh1,
    const float* __restrict__ Wh2, const float* __restrict__ Wh3,
    float* __restrict__ out, int t)
{
    const int tid = threadIdx.x;
    const int j0  = blockIdx.x * 32;   // hidden-unit tile (12 tiles)
    const int s0  = blockIdx.y * 64;   // sequence tile   (12 tiles)
    const int d   = blockIdx.z;        // direction

    const float* Wh   = (d == 0) ? Wh0 : (d == 1) ? Wh1 : (d == 2) ? Wh2 : Wh3;
    const float* hin  = g_h[d][t & 1];
    float*       hout = g_h[d][(t + 1) & 1];
    float*       cbuf = g_c[d];
    const float* zslab = g_z + (long)(d * TT + t) * NSEQ * G4;

    __shared__ float As[8][64];    // [k][seq]
    __shared__ float Bs[8][128];   // [k][unit*4 + gate]

    const int ty = tid / 32;       // 0..7
    const int tx = tid % 32;       // 0..31

    ull acc2[8][2];                // [row][(i,f) | (c,o)]
#pragma unroll
    for (int r = 0; r < 8; r++) { acc2[r][0] = 0ULL; acc2[r][1] = 0ULL; }

    if (t > 0) {
        const int arow = tid / 2;          // 0..63 (only tid<128 load A)
        const int ak   = (tid & 1) * 4;

        for (int k = 0; k < HID; k += 8) {
            float4 av = make_float4(0.f, 0.f, 0.f, 0.f);
            if (tid < 128)
                av = *(const float4*)(hin + (s0 + arow) * HID + k + ak);
            const float* wrow = Wh + (long)(k + ty) * G4 + j0 + tx;
            float bv0 = wrow[0 * HID];
            float bv1 = wrow[1 * HID];
            float bv2 = wrow[2 * HID];
            float bv3 = wrow[3 * HID];
            __syncthreads();
            if (tid < 128) {
                As[ak + 0][arow] = av.x;
                As[ak + 1][arow] = av.y;
                As[ak + 2][arow] = av.z;
                As[ak + 3][arow] = av.w;
            }
            *(float4*)&Bs[ty][tx * 4] = make_float4(bv0, bv1, bv2, bv3);
            __syncthreads();
#pragma unroll
            for (int kk = 0; kk < 8; kk++) {
                union { float4 f4; ull u2[2]; } bu;
                bu.f4 = *(const float4*)&Bs[kk][tx * 4];
                float a[8];
                *(float4*)&a[0] = *(const float4*)&As[kk][ty * 8];
                *(float4*)&a[4] = *(const float4*)&As[kk][ty * 8 + 4];
#pragma unroll
                for (int r = 0; r < 8; r++) {
                    ull ad = pack_dup(a[r]);
                    ffma2(acc2[r][0], ad, bu.u2[0]);
                    ffma2(acc2[r][1], ad, bu.u2[1]);
                }
            }
        }
    }

    const int j = j0 + tx;
#pragma unroll
    for (int r = 0; r < 8; r++) {
        const int s = s0 + ty * 8 + r;
        const float* zr = zslab + (long)s * G4 + j;
        union { ull u; float2 f; } u01, u23;
        u01.u = acc2[r][0];
        u23.u = acc2[r][1];
        float gi = u01.f.x + zr[0 * HID];
        float gf = u01.f.y + zr[1 * HID];
        float gc = u23.f.x + zr[2 * HID];
        float go = u23.f.y + zr[3 * HID];

        float i_ = 1.0f / (1.0f + __expf(-gi));
        float f_ = 1.0f / (1.0f + __expf(-gf));
        float cd = tanh_fast(gc);
        float o_ = 1.0f / (1.0f + __expf(-go));

        float cprev = (t > 0) ? cbuf[s * HID + j] : 0.0f;
        float cn = f_ * cprev + i_ * cd;
        cbuf[s * HID + j] = cn;
        float h = o_ * tanh_fast(cn);
        hout[s * HID + j] = h;

        // scatter to output: channel block = d*HID
        const int bb = s / 24;
        const int q  = s - bb * 24;
        int hg, wg;
        if (d == 0)      { hg = q; wg = t;            }
        else if (d == 1) { hg = q; wg = (TT - 1) - t; }
        else if (d == 2) { wg = q; hg = t;            }
        else             { wg = q; hg = (TT - 1) - t; }
        out[(long)((bb * HG + hg) * WG + wg) * G4 + d * HID + j] = h;
    }
}

// ---------------------------------------------------------------------------
// Launch
// ---------------------------------------------------------------------------
extern "C" void kernel_launch(void* const* d_in, const int* in_sizes, int n_in,
                              void* d_out, int out_size) {
    (void)in_sizes; (void)n_in; (void)out_size;
    const float* X     = (const float*)d_in[0];
    const float* hf_Wx = (const float*)d_in[1];
    const float* hf_Wh = (const float*)d_in[2];
    const float* hf_b  = (const float*)d_in[3];
    const float* hb_Wx = (const float*)d_in[4];
    const float* hb_Wh = (const float*)d_in[5];
    const float* hb_b  = (const float*)d_in[6];
    const float* vf_Wx = (const float*)d_in[7];
    const float* vf_Wh = (const float*)d_in[8];
    const float* vf_b  = (const float*)d_in[9];
    const float* vb_Wx = (const float*)d_in[10];
    const float* vb_Wh = (const float*)d_in[11];
    const float* vb_b  = (const float*)d_in[12];
    float* out = (float*)d_out;

    // 1. input projection for all 4 directions
    input_gemm_kernel<<<dim3(48, 144), 256>>>(
        X, hf_Wx, hb_Wx, vf_Wx, vb_Wx, hf_b, hb_b, vf_b, vb_b);

    // 2. 24 recurrent steps, all 4 directions per launch (t=0 skips the GEMM
    //    and zero-initializes h/c implicitly)
    for (int t = 0; t < TT; t++) {
        lstm_step_kernel<<<dim3(HID / 32, NSEQ / 64, 4), 256>>>(
            hf_Wh, hb_Wh, vf_Wh, vb_Wh, out, t);
    }
}